// round 12
// baseline (speedup 1.0000x reference)
#include <cuda_runtime.h>
#include <cuda_fp16.h>
#include <cstdint>

#define B_   8
#define N_   1024
#define DIN  768
#define DOUT 768
#define H_   12
#define DH   64
#define M_   (B_ * N_)   // 8192
#define K_   768

// Scratch (allocation-free: __device__ globals), all fp16 operands
__device__ __align__(128) __half g_X [M_ * K_];
__device__ __align__(128) __half g_Wq[DOUT * DIN];
__device__ __align__(128) __half g_Wk[DOUT * DIN];
__device__ __align__(128) __half g_Wv[DOUT * DIN];
__device__ __align__(128) __half g_Wo[DOUT * DIN];
__device__ __align__(128) __half g_Q[B_ * H_ * N_ * DH];   // [b][h][n][e], pre-scaled
__device__ __align__(128) __half g_K[B_ * H_ * N_ * DH];   // [b][h][n][e]
__device__ __align__(128) __half g_V[B_ * H_ * DH * N_];   // [b][h][e][n] transposed
__device__ __align__(128) __half g_A[B_ * N_ * DOUT];      // attn out [b][n][h*64+e]

// ===========================================================================
// Helpers
// ===========================================================================
__device__ __forceinline__ uint32_t h2_as_u32(__half2 h) {
    union { __half2 h; uint32_t u; } c; c.h = h; return c.u;
}
__device__ __forceinline__ __half2 u32_as_h2(uint32_t u) {
    union { uint32_t u; __half2 h; } c; c.u = u; return c.h;
}
__device__ __forceinline__ uint32_t pack_h2(float lo, float hi) {
    return h2_as_u32(__float22half2_rn(make_float2(lo, hi)));
}

__device__ __forceinline__ uint32_t smem_u32(const void* p) {
    uint32_t a;
    asm("{ .reg .u64 t; cvta.to.shared.u64 t, %1; cvt.u32.u64 %0, t; }"
        : "=r"(a) : "l"(p));
    return a;
}

// packed fp16x2 exp2
__device__ __forceinline__ uint32_t ex2_h2(uint32_t x) {
    uint32_t y;
    asm("ex2.approx.f16x2 %0, %1;" : "=r"(y) : "r"(x));
    return y;
}

__device__ __forceinline__ void ldsm4(uint32_t& r0, uint32_t& r1, uint32_t& r2, uint32_t& r3,
                                      uint32_t addr) {
    asm volatile("ldmatrix.sync.aligned.m8n8.x4.shared.b16 {%0,%1,%2,%3}, [%4];"
        : "=r"(r0), "=r"(r1), "=r"(r2), "=r"(r3) : "r"(addr));
}

// m16n8k16 fp16 mma, fp32 accumulate
__device__ __forceinline__ void mma_f16(float c[4], const uint32_t a[4],
                                        uint32_t b0, uint32_t b1) {
    asm volatile(
        "mma.sync.aligned.m16n8k16.row.col.f32.f16.f16.f32 "
        "{%0,%1,%2,%3}, {%4,%5,%6,%7}, {%8,%9}, {%0,%1,%2,%3};"
        : "+f"(c[0]), "+f"(c[1]), "+f"(c[2]), "+f"(c[3])
        : "r"(a[0]), "r"(a[1]), "r"(a[2]), "r"(a[3]), "r"(b0), "r"(b1));
}

// m16n8k16 fp16 mma, fp16 accumulate (2x rate)
__device__ __forceinline__ void mma_f16acc(uint32_t c[2], const uint32_t a[4],
                                           uint32_t b0, uint32_t b1) {
    asm volatile(
        "mma.sync.aligned.m16n8k16.row.col.f16.f16.f16.f16 "
        "{%0,%1}, {%2,%3,%4,%5}, {%6,%7}, {%0,%1};"
        : "+r"(c[0]), "+r"(c[1])
        : "r"(a[0]), "r"(a[1]), "r"(a[2]), "r"(a[3]), "r"(b0), "r"(b1));
}

__device__ __forceinline__ void cp16(uint32_t saddr, const void* gptr) {
    asm volatile("cp.async.cg.shared.global [%0], [%1], 16;"
        :: "r"(saddr), "l"(gptr) : "memory");
}
#define CP_COMMIT() asm volatile("cp.async.commit_group;" ::: "memory")
#define CP_WAIT0()  asm volatile("cp.async.wait_group 0;" ::: "memory")
#define CP_WAIT1()  asm volatile("cp.async.wait_group 1;" ::: "memory")

// ===========================================================================
// Pre-round x and weights to fp16 (one pass)
// ===========================================================================
__global__ __launch_bounds__(256)
void preround(const float* __restrict__ x,
              const float* __restrict__ wq, const float* __restrict__ wk,
              const float* __restrict__ wv, const float* __restrict__ wo)
{
    constexpr int XV = M_ * K_ / 8;
    constexpr int WV = DOUT * DIN / 8;
    constexpr int TOT = XV + 4 * WV;
    for (int i = blockIdx.x * blockDim.x + threadIdx.x; i < TOT;
         i += gridDim.x * blockDim.x) {
        const float4* src; __half* dst; int off;
        if (i < XV) { src = (const float4*)x; dst = g_X; off = i; }
        else {
            int j = i - XV, seg = j / WV; off = j % WV;
            src = (seg == 0) ? (const float4*)wq : (seg == 1) ? (const float4*)wk
                : (seg == 2) ? (const float4*)wv : (const float4*)wo;
            dst = (seg == 0) ? g_Wq : (seg == 1) ? g_Wk
                : (seg == 2) ? g_Wv : g_Wo;
        }
        float4 v0 = src[2 * off];
        float4 v1 = src[2 * off + 1];
        uint4 u;
        u.x = pack_h2(v0.x, v0.y);
        u.y = pack_h2(v0.z, v0.w);
        u.z = pack_h2(v1.x, v1.y);
        u.w = pack_h2(v1.z, v1.w);
        *(uint4*)(dst + 8 * (size_t)off) = u;
    }
}

// ===========================================================================
// QKV GEMM: fp16 accumulate; epilogue COALESCED via smem staging.
// cp.async 3-stage, 256 threads (8 warps 4x2), warp tile 32x64, k-tile 64.
// Epilogue: stage tile in smem ([m][c] for Q/K, [c][m] for V, pad 136) then
// uint4 row writes -> no 2-byte scatter (kills ~16x DRAM sector amplification
// on V and 2x on Q/K).
// ===========================================================================
#define GEMM_SMEM (3 * 32768)
#define EPAD 136   // halfs per staged row (pad vs 128: conflict-free, 16B-aligned)

__global__ __launch_bounds__(256, 2)
void gemm_qkv(const float* __restrict__ bo, float* __restrict__ out)
{
    (void)bo; (void)out;
    extern __shared__ char smc[];
    const uint32_t sbase = smem_u32(smc);

    const int tid  = threadIdx.x;
    const int wid  = tid >> 5;
    const int lane = tid & 31;
    const int wm   = wid >> 1;
    const int wn   = wid & 1;

    const int m0    = blockIdx.x * 128;
    const int ntile = blockIdx.y;
    const int wsel  = ntile / 6;
    const __half* Bmat = (wsel == 0) ? g_Wq : (wsel == 1) ? g_Wk : g_Wv;
    const int c0 = (ntile % 6) * 128;

    const __half* Ag = g_X + (size_t)m0 * K_;
    const __half* Bg = Bmat + (size_t)c0 * K_;

    uint32_t acc[2][8][2];
#pragma unroll
    for (int i = 0; i < 2; i++)
#pragma unroll
        for (int j = 0; j < 8; j++) { acc[i][j][0] = 0u; acc[i][j][1] = 0u; }

    const int frow = ((lane >> 3) & 1) * 8 + (lane & 7);
    const int fch  = lane >> 4;
    const int rowA_base = wm * 32 + frow;
    const int rowB_base = wn * 64 + frow;

    constexpr int KT = K_ / 64;   // 12

    auto issue = [&](int kt) {
        const uint32_t so = sbase + (uint32_t)(kt % 3) * 32768u;
#pragma unroll
        for (int i = 0; i < 4; i++) {
            int idx = i * 256 + tid;
            int r = idx >> 3, ch = idx & 7;
            int sw = ch ^ (r & 7);
            cp16(so + (uint32_t)(r * 128 + sw * 16),
                 Ag + (size_t)r * K_ + kt * 64 + ch * 8);
            cp16(so + 16384u + (uint32_t)(r * 128 + sw * 16),
                 Bg + (size_t)r * K_ + kt * 64 + ch * 8);
        }
    };

    issue(0); CP_COMMIT();
    issue(1); CP_COMMIT();

    for (int kt = 0; kt < KT; kt++) {
        CP_WAIT1();
        __syncthreads();

        if (kt + 2 < KT) issue(kt + 2);
        CP_COMMIT();

        const uint32_t sAo = sbase + (uint32_t)(kt % 3) * 32768u;
        const uint32_t sBo = sAo + 16384u;
#pragma unroll
        for (int ks = 0; ks < 4; ks++) {
            uint32_t afr[2][4];
#pragma unroll
            for (int mi = 0; mi < 2; mi++) {
                int row = rowA_base + mi * 16;
                int ch  = ks * 2 + fch;
                int sw  = ch ^ (row & 7);
                ldsm4(afr[mi][0], afr[mi][1], afr[mi][2], afr[mi][3],
                      sAo + (uint32_t)(row * 128 + sw * 16));
            }
            uint32_t bfr[4][4];
#pragma unroll
            for (int nj = 0; nj < 4; nj++) {
                int row = rowB_base + nj * 16;
                int ch  = ks * 2 + fch;
                int sw  = ch ^ (row & 7);
                ldsm4(bfr[nj][0], bfr[nj][1], bfr[nj][2], bfr[nj][3],
                      sBo + (uint32_t)(row * 128 + sw * 16));
            }
#pragma unroll
            for (int mi = 0; mi < 2; mi++)
#pragma unroll
                for (int nj = 0; nj < 4; nj++) {
                    mma_f16acc(acc[mi][nj * 2 + 0], afr[mi], bfr[nj][0], bfr[nj][2]);
                    mma_f16acc(acc[mi][nj * 2 + 1], afr[mi], bfr[nj][1], bfr[nj][3]);
                }
        }
    }

    // ---- Coalesced epilogue: stage in smem, then uint4 row writes ----
    __syncthreads();   // mainloop smem dead for ALL warps before reuse
    __half* sE = (__half*)smc;
    const int g = lane >> 2, t = lane & 3;
    const float qscale = 0.125f * 1.44269504088896f;
    const int b  = m0 >> 10;                 // block fits in one batch
    const int n0 = m0 & (N_ - 1);

    if (wsel < 2) {
        // Stage [m][c] (scaled); conflict-free u32 stores with EPAD
        const float sc = (wsel == 0) ? qscale : 1.f;
#pragma unroll
        for (int mi = 0; mi < 2; mi++)
#pragma unroll
            for (int nt = 0; nt < 8; nt++) {
                int cl = wn * 64 + nt * 8 + t * 2;
#pragma unroll
                for (int rr = 0; rr < 2; rr++) {
                    int ml = wm * 32 + mi * 16 + g + rr * 8;
                    float2 f = __half22float2(u32_as_h2(acc[mi][nt][rr]));
                    *(uint32_t*)(sE + ml * EPAD + cl) = pack_h2(f.x * sc, f.y * sc);
                }
            }
        __syncthreads();
        // Write: row ml = tid>>1, head-segment seg = tid&1 (64 halfs = 8 uint4)
        __half* outp = (wsel == 0) ? g_Q : g_K;
        int ml = tid >> 1, seg = tid & 1;
        int h = (c0 >> 6) + seg;
        const uint4* src = (const uint4*)(sE + ml * EPAD + seg * 64);
        uint4* dst = (uint4*)(outp + (((size_t)(b * H_ + h) * N_ + (n0 + ml)) * DH));
#pragma unroll
        for (int i = 0; i < 8; i++) dst[i] = src[i];
    } else {
        // Stage [c][m] (transposed) with scalar half stores
#pragma unroll
        for (int mi = 0; mi < 2; mi++)
#pragma unroll
            for (int nt = 0; nt < 8; nt++) {
                int cl = wn * 64 + nt * 8 + t * 2;
#pragma unroll
                for (int rr = 0; rr < 2; rr++) {
                    int ml = wm * 32 + mi * 16 + g + rr * 8;
                    __half2 hv = u32_as_h2(acc[mi][nt][rr]);
                    sE[cl * EPAD + ml]       = __low2half(hv);
                    sE[(cl + 1) * EPAD + ml] = __high2half(hv);
                }
            }
        __syncthreads();
        // Write: row cl = tid>>1 (one (h,e) row), n-segment seg = tid&1
        int cl = tid >> 1, seg = tid & 1;
        int cw = c0 + cl;
        int h = cw >> 6, e = cw & 63;
        const uint4* src = (const uint4*)(sE + cl * EPAD + seg * 64);
        uint4* dst = (uint4*)(g_V + (((size_t)(b * H_ + h) * DH + e) * N_) + n0 + seg * 64);
#pragma unroll
        for (int i = 0; i < 8; i++) dst[i] = src[i];
    }
}

// ===========================================================================
// Output-proj GEMM: fp32 accumulate (final output precision). Unchanged.
// ===========================================================================
__global__ __launch_bounds__(256, 2)
void gemm_out(const float* __restrict__ bo, float* __restrict__ out)
{
    extern __shared__ char smc[];
    const uint32_t sbase = smem_u32(smc);

    const int tid  = threadIdx.x;
    const int wid  = tid >> 5;
    const int lane = tid & 31;
    const int wm   = wid >> 1;
    const int wn   = wid & 1;

    const int m0 = blockIdx.x * 128;
    const int c0 = blockIdx.y * 128;

    const __half* Ag = g_A + (size_t)m0 * K_;
    const __half* Bg = g_Wo + (size_t)c0 * K_;

    float acc[2][8][4];
#pragma unroll
    for (int i = 0; i < 2; i++)
#pragma unroll
        for (int j = 0; j < 8; j++)
#pragma unroll
            for (int k = 0; k < 4; k++) acc[i][j][k] = 0.f;

    const int frow = ((lane >> 3) & 1) * 8 + (lane & 7);
    const int fch  = lane >> 4;
    const int rowA_base = wm * 32 + frow;
    const int rowB_base = wn * 64 + frow;

    constexpr int KT = K_ / 64;

    auto issue = [&](int kt) {
        const uint32_t so = sbase + (uint32_t)(kt % 3) * 32768u;
#pragma unroll
        for (int i = 0; i < 4; i++) {
            int idx = i * 256 + tid;
            int r = idx >> 3, ch = idx & 7;
            int sw = ch ^ (r & 7);
            cp16(so + (uint32_t)(r * 128 + sw * 16),
                 Ag + (size_t)r * K_ + kt * 64 + ch * 8);
            cp16(so + 16384u + (uint32_t)(r * 128 + sw * 16),
                 Bg + (size_t)r * K_ + kt * 64 + ch * 8);
        }
    };

    issue(0); CP_COMMIT();
    issue(1); CP_COMMIT();

    for (int kt = 0; kt < KT; kt++) {
        CP_WAIT1();
        __syncthreads();

        if (kt + 2 < KT) issue(kt + 2);
        CP_COMMIT();

        const uint32_t sAo = sbase + (uint32_t)(kt % 3) * 32768u;
        const uint32_t sBo = sAo + 16384u;
#pragma unroll
        for (int ks = 0; ks < 4; ks++) {
            uint32_t afr[2][4];
#pragma unroll
            for (int mi = 0; mi < 2; mi++) {
                int row = rowA_base + mi * 16;
                int ch  = ks * 2 + fch;
                int sw  = ch ^ (row & 7);
                ldsm4(afr[mi][0], afr[mi][1], afr[mi][2], afr[mi][3],
                      sAo + (uint32_t)(row * 128 + sw * 16));
            }
            uint32_t bfr[4][4];
#pragma unroll
            for (int nj = 0; nj < 4; nj++) {
                int row = rowB_base + nj * 16;
                int ch  = ks * 2 + fch;
                int sw  = ch ^ (row & 7);
                ldsm4(bfr[nj][0], bfr[nj][1], bfr[nj][2], bfr[nj][3],
                      sBo + (uint32_t)(row * 128 + sw * 16));
            }
#pragma unroll
            for (int mi = 0; mi < 2; mi++)
#pragma unroll
                for (int nj = 0; nj < 4; nj++) {
                    mma_f16(acc[mi][nj * 2 + 0], afr[mi], bfr[nj][0], bfr[nj][2]);
                    mma_f16(acc[mi][nj * 2 + 1], afr[mi], bfr[nj][1], bfr[nj][3]);
                }
        }
    }

    const int g = lane >> 2, t = lane & 3;
#pragma unroll
    for (int mi = 0; mi < 2; mi++) {
#pragma unroll
        for (int nt = 0; nt < 8; nt++) {
            int cw = c0 + wn * 64 + nt * 8 + t * 2;
            int r0 = m0 + wm * 32 + mi * 16 + g;
            float2 bias = *(const float2*)(bo + cw);
#pragma unroll
            for (int rr = 0; rr < 2; rr++) {
                int m = r0 + rr * 8;
                float2 v = make_float2(acc[mi][nt][rr * 2] + bias.x,
                                       acc[mi][nt][rr * 2 + 1] + bias.y);
                *(float2*)(out + (size_t)m * DOUT + cw) = v;
            }
        }
    }
}

// ===========================================================================
// Flash attention (unchanged from round 11): S fp16-accum (C-frags ARE the
// PV A-frags), packed ex2, unnormalized softmax, PV fp32-accum.
// smem: Q @0 (16KB), K @16384 (2x8KB), V @32768 (2x8KB) = 48KB
// ===========================================================================
#define AQ_OFF 0u
#define AK_OFF 16384u
#define AV_OFF 32768u
#define ATTN_SMEM 49152

__global__ __launch_bounds__(256, 2)
void attn_mma()
{
    extern __shared__ char smc[];
    const uint32_t sbase = smem_u32(smc);

    const int qt = blockIdx.x;        // 0..7
    const int bh = blockIdx.y;        // 0..95
    const __half* Qb = g_Q + (size_t)bh * N_ * DH;
    const __half* Kb = g_K + (size_t)bh * N_ * DH;
    const __half* Vb = g_V + (size_t)bh * DH * N_;   // [e][n]

    const int tid  = threadIdx.x;
    const int wid  = tid >> 5;
    const int lane = tid & 31;
    const int g    = lane >> 2;
    const int t    = lane & 3;

    const int frow = ((lane >> 3) & 1) * 8 + (lane & 7);
    const int fch  = lane >> 4;
    const int rowAf = wid * 16 + frow;   // Q A-frag row

    // ---- prologue: Q tile + K/V tile 0 ----
#pragma unroll
    for (int i = 0; i < 4; i++) {
        int idx = i * 256 + tid;
        int r = idx >> 3, ch = idx & 7;
        cp16(sbase + AQ_OFF + (uint32_t)(r * 128 + ((ch ^ (r & 7)) * 16)),
             Qb + (size_t)(qt * 128 + r) * DH + ch * 8);
    }
#pragma unroll
    for (int i = 0; i < 2; i++) {
        int idx = i * 256 + tid;
        int r = idx >> 3, ch = idx & 7;
        uint32_t so = (uint32_t)(r * 128 + ((ch ^ (r & 7)) * 16));
        cp16(sbase + AK_OFF + so, Kb + (size_t)r * DH + ch * 8);
        cp16(sbase + AV_OFF + so, Vb + (size_t)r * N_ + ch * 8);
    }
    CP_COMMIT();

    float l_r[2] = {0.f, 0.f};
    float o[8][4];
#pragma unroll
    for (int i = 0; i < 8; i++)
#pragma unroll
        for (int j = 0; j < 4; j++) o[i][j] = 0.f;

    uint32_t qfr[4][4];   // cached Q fragments

    for (int kt = 0; kt < N_ / 64; kt++) {
        CP_WAIT0();
        __syncthreads();   // K/V(kt) visible; other buffer's readers done

        // prefetch next K/V into the other buffer
        if (kt + 1 < N_ / 64) {
            const __half* Kn = Kb + (size_t)(kt + 1) * 64 * DH;
            const __half* Vn = Vb + (size_t)(kt + 1) * 64;
            const uint32_t bufo = (uint32_t)((kt + 1) & 1) * 8192u;
#pragma unroll
            for (int i = 0; i < 2; i++) {
                int idx = i * 256 + tid;
                int r = idx >> 3, ch = idx & 7;
                uint32_t so = (uint32_t)(r * 128 + ((ch ^ (r & 7)) * 16));
                cp16(sbase + AK_OFF + bufo + so, Kn + (size_t)r * DH + ch * 8);
                cp16(sbase + AV_OFF + bufo + so, Vn + (size_t)r * N_ + ch * 8);
            }
        }
        CP_COMMIT();

        if (kt == 0) {
#pragma unroll
            for (int ks = 0; ks < 4; ks++) {
                int ch = ks * 2 + fch;
                int sw = ch ^ (rowAf & 7);
                ldsm4(qfr[ks][0], qfr[ks][1], qfr[ks][2], qfr[ks][3],
                      sbase + AQ_OFF + (uint32_t)(rowAf * 128 + sw * 16));
            }
        }

        const uint32_t sKo = sbase + AK_OFF + (uint32_t)(kt & 1) * 8192u;
        const uint32_t sVo = sbase + AV_OFF + (uint32_t)(kt & 1) * 8192u;

        // ---- S = Q K^T, fp16 accumulate (exp2-domain via pre-scaled Q) ----
        uint32_t s[8][2];
#pragma unroll
        for (int i = 0; i < 8; i++) { s[i][0] = 0u; s[i][1] = 0u; }

#pragma unroll
        for (int ks = 0; ks < 4; ks++) {
#pragma unroll
            for (int nj = 0; nj < 4; nj++) {
                uint32_t b[4];
                int row = nj * 16 + frow;
                int ch = ks * 2 + fch;
                int sw = ch ^ (row & 7);
                ldsm4(b[0], b[1], b[2], b[3], sKo + (uint32_t)(row * 128 + sw * 16));
                mma_f16acc(s[nj * 2 + 0], qfr[ks], b[0], b[2]);
                mma_f16acc(s[nj * 2 + 1], qfr[ks], b[1], b[3]);
            }
        }

        // ---- packed exp2; fp32 row sums ----
#pragma unroll
        for (int nt = 0; nt < 8; nt++) {
            s[nt][0] = ex2_h2(s[nt][0]);
            s[nt][1] = ex2_h2(s[nt][1]);
            float2 f0 = __half22float2(u32_as_h2(s[nt][0]));
            float2 f1 = __half22float2(u32_as_h2(s[nt][1]));
            l_r[0] += f0.x + f0.y;
            l_r[1] += f1.x + f1.y;
        }

        // ---- O += P @ V; P A-frags = s regs directly (layout identity) ----
#pragma unroll
        for (int ks = 0; ks < 4; ks++) {
            uint32_t a[4];
            a[0] = s[2 * ks][0];
            a[1] = s[2 * ks][1];
            a[2] = s[2 * ks + 1][0];
            a[3] = s[2 * ks + 1][1];
#pragma unroll
            for (int nj = 0; nj < 4; nj++) {
                uint32_t b[4];
                int row = nj * 16 + frow;
                int ch = ks * 2 + fch;
                int sw = ch ^ (row & 7);
                ldsm4(b[0], b[1], b[2], b[3], sVo + (uint32_t)(row * 128 + sw * 16));
                mma_f16(o[nj * 2 + 0], a, b[0], b[2]);
                mma_f16(o[nj * 2 + 1], a, b[1], b[3]);
            }
        }
    }

    // ---- final row-sum reduction + epilogue -> g_A (fp16) ----
#pragma unroll
    for (int r = 0; r < 2; r++) {
        l_r[r] += __shfl_xor_sync(0xffffffffu, l_r[r], 1);
        l_r[r] += __shfl_xor_sync(0xffffffffu, l_r[r], 2);
    }
    const int b_ = bh / H_, h = bh % H_;
    const float inv0 = 1.f / l_r[0];
    const float inv1 = 1.f / l_r[1];
    const int n0 = qt * 128 + wid * 16 + g;
    const int n1 = n0 + 8;
#pragma unroll
    for (int nt = 0; nt < 8; nt++) {
        int e = nt * 8 + t * 2;
        *(__half2*)(g_A + ((size_t)(b_ * N_ + n0) * DOUT) + h * DH + e) =
            __float22half2_rn(make_float2(o[nt][0] * inv0, o[nt][1] * inv0));
        *(__half2*)(g_A + ((size_t)(b_ * N_ + n1) * DOUT) + h * DH + e) =
            __float22half2_rn(make_float2(o[nt][2] * inv1, o[nt][3] * inv1));
    }
}

// ===========================================================================
extern "C" void kernel_launch(void* const* d_in, const int* in_sizes, int n_in,
                              void* d_out, int out_size)
{
    (void)in_sizes; (void)n_in; (void)out_size;
    const float* x  = (const float*)d_in[0];
    const float* Wq = (const float*)d_in[1];
    const float* Wk = (const float*)d_in[2];
    const float* Wv = (const float*)d_in[3];
    const float* Wo = (const float*)d_in[4];
    const float* bo = (const float*)d_in[5];
    float* out = (float*)d_out;

    cudaFuncSetAttribute(gemm_qkv, cudaFuncAttributeMaxDynamicSharedMemorySize, GEMM_SMEM);
    cudaFuncSetAttribute(gemm_out, cudaFuncAttributeMaxDynamicSharedMemorySize, GEMM_SMEM);
    cudaFuncSetAttribute(attn_mma, cudaFuncAttributeMaxDynamicSharedMemorySize, ATTN_SMEM);

    preround<<<2112, 256>>>(x, Wq, Wk, Wv, Wo);
    gemm_qkv<<<dim3(M_ / 128, 18), 256, GEMM_SMEM>>>(bo, out);
    attn_mma<<<dim3(N_ / 128, B_ * H_), 256, ATTN_SMEM>>>();
    gemm_out<<<dim3(M_ / 128, 6), 256, GEMM_SMEM>>>(bo, out);
}

// round 13
// speedup vs baseline: 1.0786x; 1.0786x over previous
#include <cuda_runtime.h>
#include <cuda_fp16.h>
#include <cstdint>

#define B_   8
#define N_   1024
#define DIN  768
#define DOUT 768
#define H_   12
#define DH   64
#define M_   (B_ * N_)   // 8192
#define K_   768

// Scratch (allocation-free: __device__ globals), all fp16 operands
__device__ __align__(128) __half g_X [M_ * K_];
__device__ __align__(128) __half g_Wq[DOUT * DIN];
__device__ __align__(128) __half g_Wk[DOUT * DIN];
__device__ __align__(128) __half g_Wv[DOUT * DIN];
__device__ __align__(128) __half g_Wo[DOUT * DIN];
__device__ __align__(128) __half g_Q[B_ * H_ * N_ * DH];   // [b][h][n][e], pre-scaled
__device__ __align__(128) __half g_K[B_ * H_ * N_ * DH];   // [b][h][n][e]
__device__ __align__(128) __half g_V[B_ * H_ * DH * N_];   // [b][h][e][n] transposed
__device__ __align__(128) __half g_A[B_ * N_ * DOUT];      // attn out [b][n][h*64+e]

// ===========================================================================
// Helpers
// ===========================================================================
__device__ __forceinline__ uint32_t h2_as_u32(__half2 h) {
    union { __half2 h; uint32_t u; } c; c.h = h; return c.u;
}
__device__ __forceinline__ __half2 u32_as_h2(uint32_t u) {
    union { uint32_t u; __half2 h; } c; c.u = u; return c.h;
}
__device__ __forceinline__ uint32_t pack_h2(float lo, float hi) {
    return h2_as_u32(__float22half2_rn(make_float2(lo, hi)));
}

__device__ __forceinline__ uint32_t smem_u32(const void* p) {
    uint32_t a;
    asm("{ .reg .u64 t; cvta.to.shared.u64 t, %1; cvt.u32.u64 %0, t; }"
        : "=r"(a) : "l"(p));
    return a;
}

// packed fp16x2 exp2
__device__ __forceinline__ uint32_t ex2_h2(uint32_t x) {
    uint32_t y;
    asm("ex2.approx.f16x2 %0, %1;" : "=r"(y) : "r"(x));
    return y;
}

__device__ __forceinline__ void ldsm4(uint32_t& r0, uint32_t& r1, uint32_t& r2, uint32_t& r3,
                                      uint32_t addr) {
    asm volatile("ldmatrix.sync.aligned.m8n8.x4.shared.b16 {%0,%1,%2,%3}, [%4];"
        : "=r"(r0), "=r"(r1), "=r"(r2), "=r"(r3) : "r"(addr));
}

// m16n8k16 fp16 mma, fp32 accumulate
__device__ __forceinline__ void mma_f16(float c[4], const uint32_t a[4],
                                        uint32_t b0, uint32_t b1) {
    asm volatile(
        "mma.sync.aligned.m16n8k16.row.col.f32.f16.f16.f32 "
        "{%0,%1,%2,%3}, {%4,%5,%6,%7}, {%8,%9}, {%0,%1,%2,%3};"
        : "+f"(c[0]), "+f"(c[1]), "+f"(c[2]), "+f"(c[3])
        : "r"(a[0]), "r"(a[1]), "r"(a[2]), "r"(a[3]), "r"(b0), "r"(b1));
}

// m16n8k16 fp16 mma, fp16 accumulate (2x rate)
__device__ __forceinline__ void mma_f16acc(uint32_t c[2], const uint32_t a[4],
                                           uint32_t b0, uint32_t b1) {
    asm volatile(
        "mma.sync.aligned.m16n8k16.row.col.f16.f16.f16.f16 "
        "{%0,%1}, {%2,%3,%4,%5}, {%6,%7}, {%0,%1};"
        : "+r"(c[0]), "+r"(c[1])
        : "r"(a[0]), "r"(a[1]), "r"(a[2]), "r"(a[3]), "r"(b0), "r"(b1));
}

__device__ __forceinline__ void cp16(uint32_t saddr, const void* gptr) {
    asm volatile("cp.async.cg.shared.global [%0], [%1], 16;"
        :: "r"(saddr), "l"(gptr) : "memory");
}
#define CP_COMMIT() asm volatile("cp.async.commit_group;" ::: "memory")
#define CP_WAIT0()  asm volatile("cp.async.wait_group 0;" ::: "memory")
#define CP_WAIT1()  asm volatile("cp.async.wait_group 1;" ::: "memory")

// ===========================================================================
// Pre-round x and weights to fp16 (one pass)
// ===========================================================================
__global__ __launch_bounds__(256)
void preround(const float* __restrict__ x,
              const float* __restrict__ wq, const float* __restrict__ wk,
              const float* __restrict__ wv, const float* __restrict__ wo)
{
    constexpr int XV = M_ * K_ / 8;
    constexpr int WV = DOUT * DIN / 8;
    constexpr int TOT = XV + 4 * WV;
    for (int i = blockIdx.x * blockDim.x + threadIdx.x; i < TOT;
         i += gridDim.x * blockDim.x) {
        const float4* src; __half* dst; int off;
        if (i < XV) { src = (const float4*)x; dst = g_X; off = i; }
        else {
            int j = i - XV, seg = j / WV; off = j % WV;
            src = (seg == 0) ? (const float4*)wq : (seg == 1) ? (const float4*)wk
                : (seg == 2) ? (const float4*)wv : (const float4*)wo;
            dst = (seg == 0) ? g_Wq : (seg == 1) ? g_Wk
                : (seg == 2) ? g_Wv : g_Wo;
        }
        float4 v0 = src[2 * off];
        float4 v1 = src[2 * off + 1];
        uint4 u;
        u.x = pack_h2(v0.x, v0.y);
        u.y = pack_h2(v0.z, v0.w);
        u.z = pack_h2(v1.x, v1.y);
        u.w = pack_h2(v1.z, v1.w);
        *(uint4*)(dst + 8 * (size_t)off) = u;
    }
}

// ===========================================================================
// QKV GEMM (round-11 version: fp16 accumulate, direct epilogue).
// cp.async 3-stage, 256 threads (8 warps 4x2), warp tile 32x64, k-tile 64.
// ===========================================================================
#define GEMM_SMEM (3 * 32768)

__global__ __launch_bounds__(256, 2)
void gemm_qkv()
{
    extern __shared__ char smc[];
    const uint32_t sbase = smem_u32(smc);

    const int tid  = threadIdx.x;
    const int wid  = tid >> 5;
    const int lane = tid & 31;
    const int wm   = wid >> 1;
    const int wn   = wid & 1;

    const int m0    = blockIdx.x * 128;
    const int ntile = blockIdx.y;
    const int wsel  = ntile / 6;
    const __half* Bmat = (wsel == 0) ? g_Wq : (wsel == 1) ? g_Wk : g_Wv;
    const int c0 = (ntile % 6) * 128;

    const __half* Ag = g_X + (size_t)m0 * K_;
    const __half* Bg = Bmat + (size_t)c0 * K_;

    uint32_t acc[2][8][2];
#pragma unroll
    for (int i = 0; i < 2; i++)
#pragma unroll
        for (int j = 0; j < 8; j++) { acc[i][j][0] = 0u; acc[i][j][1] = 0u; }

    const int frow = ((lane >> 3) & 1) * 8 + (lane & 7);
    const int fch  = lane >> 4;
    const int rowA_base = wm * 32 + frow;
    const int rowB_base = wn * 64 + frow;

    constexpr int KT = K_ / 64;   // 12

    auto issue = [&](int kt) {
        const uint32_t so = sbase + (uint32_t)(kt % 3) * 32768u;
#pragma unroll
        for (int i = 0; i < 4; i++) {
            int idx = i * 256 + tid;
            int r = idx >> 3, ch = idx & 7;
            int sw = ch ^ (r & 7);
            cp16(so + (uint32_t)(r * 128 + sw * 16),
                 Ag + (size_t)r * K_ + kt * 64 + ch * 8);
            cp16(so + 16384u + (uint32_t)(r * 128 + sw * 16),
                 Bg + (size_t)r * K_ + kt * 64 + ch * 8);
        }
    };

    issue(0); CP_COMMIT();
    issue(1); CP_COMMIT();

    for (int kt = 0; kt < KT; kt++) {
        CP_WAIT1();
        __syncthreads();

        if (kt + 2 < KT) issue(kt + 2);
        CP_COMMIT();

        const uint32_t sAo = sbase + (uint32_t)(kt % 3) * 32768u;
        const uint32_t sBo = sAo + 16384u;
#pragma unroll
        for (int ks = 0; ks < 4; ks++) {
            uint32_t afr[2][4];
#pragma unroll
            for (int mi = 0; mi < 2; mi++) {
                int row = rowA_base + mi * 16;
                int ch  = ks * 2 + fch;
                int sw  = ch ^ (row & 7);
                ldsm4(afr[mi][0], afr[mi][1], afr[mi][2], afr[mi][3],
                      sAo + (uint32_t)(row * 128 + sw * 16));
            }
            uint32_t bfr[4][4];
#pragma unroll
            for (int nj = 0; nj < 4; nj++) {
                int row = rowB_base + nj * 16;
                int ch  = ks * 2 + fch;
                int sw  = ch ^ (row & 7);
                ldsm4(bfr[nj][0], bfr[nj][1], bfr[nj][2], bfr[nj][3],
                      sBo + (uint32_t)(row * 128 + sw * 16));
            }
#pragma unroll
            for (int mi = 0; mi < 2; mi++)
#pragma unroll
                for (int nj = 0; nj < 4; nj++) {
                    mma_f16acc(acc[mi][nj * 2 + 0], afr[mi], bfr[nj][0], bfr[nj][2]);
                    mma_f16acc(acc[mi][nj * 2 + 1], afr[mi], bfr[nj][1], bfr[nj][3]);
                }
        }
    }

    // Direct epilogue (round-11)
    const int g = lane >> 2, t = lane & 3;
    const float qscale = 0.125f * 1.44269504088896f;
#pragma unroll
    for (int mi = 0; mi < 2; mi++) {
#pragma unroll
        for (int nt = 0; nt < 8; nt++) {
            int cw = c0 + wn * 64 + nt * 8 + t * 2;
            int r0 = m0 + wm * 32 + mi * 16 + g;
            int h = cw >> 6, e = cw & 63;
            if (wsel < 2) {
                __half* outp = (wsel == 0) ? g_Q : g_K;
                float sc = (wsel == 0) ? qscale : 1.f;
#pragma unroll
                for (int rr = 0; rr < 2; rr++) {
                    int m = r0 + rr * 8;
                    int b = m >> 10, n = m & (N_ - 1);
                    float2 f = __half22float2(u32_as_h2(acc[mi][nt][rr]));
                    __half2 v = __float22half2_rn(make_float2(f.x * sc, f.y * sc));
                    *(__half2*)(outp + (((size_t)(b * H_ + h) * N_ + n) * DH) + e) = v;
                }
            } else {
                // V transposed: [b][h][e][n]
#pragma unroll
                for (int rr = 0; rr < 2; rr++) {
                    int m = r0 + rr * 8;
                    int b = m >> 10, n = m & (N_ - 1);
                    __half2 hv = u32_as_h2(acc[mi][nt][rr]);
                    size_t base = ((size_t)(b * H_ + h) * DH + e) * N_ + n;
                    g_V[base]      = __low2half(hv);
                    g_V[base + N_] = __high2half(hv);
                }
            }
        }
    }
}

// ===========================================================================
// Output-proj GEMM: fp32 accumulate, 128x64 tiles (grid 768 fixes the
// 1.3-wave quantization of the 384-CTA version: 2 block-rounds -> 3 of T/2).
// 256 threads = 8 warps 4x2, warp tile 32x32, k-tile 64.
// smem/stage: A 16KB @0, B 8KB @16384 -> 24KB, 3 stages = 72KB.
// ===========================================================================
#define OUT_SMEM (3 * 24576)

__global__ __launch_bounds__(256, 2)
void gemm_out(const float* __restrict__ bo, float* __restrict__ out)
{
    extern __shared__ char smc[];
    const uint32_t sbase = smem_u32(smc);

    const int tid  = threadIdx.x;
    const int wid  = tid >> 5;
    const int lane = tid & 31;
    const int wm   = wid >> 1;   // 0..3
    const int wn   = wid & 1;    // 0..1

    const int m0 = blockIdx.x * 128;
    const int c0 = blockIdx.y * 64;

    const __half* Ag = g_A + (size_t)m0 * K_;
    const __half* Bg = g_Wo + (size_t)c0 * K_;

    float acc[2][4][4];
#pragma unroll
    for (int i = 0; i < 2; i++)
#pragma unroll
        for (int j = 0; j < 4; j++)
#pragma unroll
            for (int k = 0; k < 4; k++) acc[i][j][k] = 0.f;

    const int frow = ((lane >> 3) & 1) * 8 + (lane & 7);
    const int fch  = lane >> 4;
    const int rowA_base = wm * 32 + frow;
    const int rowB_base = wn * 32 + frow;

    constexpr int KT = K_ / 64;

    auto issue = [&](int kt) {
        const uint32_t so = sbase + (uint32_t)(kt % 3) * 24576u;
        // A: 128 rows x 128B = 1024 chunks -> 4 iters
#pragma unroll
        for (int i = 0; i < 4; i++) {
            int idx = i * 256 + tid;
            int r = idx >> 3, ch = idx & 7;
            int sw = ch ^ (r & 7);
            cp16(so + (uint32_t)(r * 128 + sw * 16),
                 Ag + (size_t)r * K_ + kt * 64 + ch * 8);
        }
        // B: 64 rows x 128B = 512 chunks -> 2 iters
#pragma unroll
        for (int i = 0; i < 2; i++) {
            int idx = i * 256 + tid;
            int r = idx >> 3, ch = idx & 7;
            int sw = ch ^ (r & 7);
            cp16(so + 16384u + (uint32_t)(r * 128 + sw * 16),
                 Bg + (size_t)r * K_ + kt * 64 + ch * 8);
        }
    };

    issue(0); CP_COMMIT();
    issue(1); CP_COMMIT();

    for (int kt = 0; kt < KT; kt++) {
        CP_WAIT1();
        __syncthreads();

        if (kt + 2 < KT) issue(kt + 2);
        CP_COMMIT();

        const uint32_t sAo = sbase + (uint32_t)(kt % 3) * 24576u;
        const uint32_t sBo = sAo + 16384u;
#pragma unroll
        for (int ks = 0; ks < 4; ks++) {
            uint32_t afr[2][4];
#pragma unroll
            for (int mi = 0; mi < 2; mi++) {
                int row = rowA_base + mi * 16;
                int ch  = ks * 2 + fch;
                int sw  = ch ^ (row & 7);
                ldsm4(afr[mi][0], afr[mi][1], afr[mi][2], afr[mi][3],
                      sAo + (uint32_t)(row * 128 + sw * 16));
            }
            uint32_t bfr[2][4];
#pragma unroll
            for (int nj = 0; nj < 2; nj++) {
                int row = rowB_base + nj * 16;
                int ch  = ks * 2 + fch;
                int sw  = ch ^ (row & 7);
                ldsm4(bfr[nj][0], bfr[nj][1], bfr[nj][2], bfr[nj][3],
                      sBo + (uint32_t)(row * 128 + sw * 16));
            }
#pragma unroll
            for (int mi = 0; mi < 2; mi++)
#pragma unroll
                for (int nj = 0; nj < 2; nj++) {
                    mma_f16(acc[mi][nj * 2 + 0], afr[mi], bfr[nj][0], bfr[nj][2]);
                    mma_f16(acc[mi][nj * 2 + 1], afr[mi], bfr[nj][1], bfr[nj][3]);
                }
        }
    }

    const int g = lane >> 2, t = lane & 3;
#pragma unroll
    for (int mi = 0; mi < 2; mi++) {
#pragma unroll
        for (int nt = 0; nt < 4; nt++) {
            int cw = c0 + wn * 32 + nt * 8 + t * 2;
            int r0 = m0 + wm * 32 + mi * 16 + g;
            float2 bias = *(const float2*)(bo + cw);
#pragma unroll
            for (int rr = 0; rr < 2; rr++) {
                int m = r0 + rr * 8;
                float2 v = make_float2(acc[mi][nt][rr * 2] + bias.x,
                                       acc[mi][nt][rr * 2 + 1] + bias.y);
                *(float2*)(out + (size_t)m * DOUT + cw) = v;
            }
        }
    }
}

// ===========================================================================
// Flash attention: 64-row q-tiles, 128 threads (4 warps), 4 CTAs/SM.
// Per-warp math identical to round 11 (16 q-rows/warp). Grid 1536 halves
// the per-SM block granularity (tail imbalance 15% -> 6%).
// smem: Q @0 (8KB), K @8192 (2x8KB), V @24576 (2x8KB) = 40KB
// ===========================================================================
#define AQ_OFF 0u
#define AK_OFF 8192u
#define AV_OFF 24576u
#define ATTN_SMEM 40960

__global__ __launch_bounds__(128, 4)
void attn_mma()
{
    extern __shared__ char smc[];
    const uint32_t sbase = smem_u32(smc);

    const int qt = blockIdx.x;        // 0..15 (64 rows each)
    const int bh = blockIdx.y;        // 0..95
    const __half* Qb = g_Q + (size_t)bh * N_ * DH;
    const __half* Kb = g_K + (size_t)bh * N_ * DH;
    const __half* Vb = g_V + (size_t)bh * DH * N_;   // [e][n]

    const int tid  = threadIdx.x;
    const int wid  = tid >> 5;        // 0..3
    const int lane = tid & 31;
    const int g    = lane >> 2;
    const int t    = lane & 3;

    const int frow = ((lane >> 3) & 1) * 8 + (lane & 7);
    const int fch  = lane >> 4;
    const int rowAf = wid * 16 + frow;   // Q A-frag row (0..63)

    // ---- prologue: Q tile (8KB) + K/V tile 0 (8KB each) ----
#pragma unroll
    for (int i = 0; i < 4; i++) {
        int idx = i * 128 + tid;
        int r = idx >> 3, ch = idx & 7;
        uint32_t so = (uint32_t)(r * 128 + ((ch ^ (r & 7)) * 16));
        cp16(sbase + AQ_OFF + so, Qb + (size_t)(qt * 64 + r) * DH + ch * 8);
        cp16(sbase + AK_OFF + so, Kb + (size_t)r * DH + ch * 8);
        cp16(sbase + AV_OFF + so, Vb + (size_t)r * N_ + ch * 8);
    }
    CP_COMMIT();

    float l_r[2] = {0.f, 0.f};
    float o[8][4];
#pragma unroll
    for (int i = 0; i < 8; i++)
#pragma unroll
        for (int j = 0; j < 4; j++) o[i][j] = 0.f;

    uint32_t qfr[4][4];   // cached Q fragments

    for (int kt = 0; kt < N_ / 64; kt++) {
        CP_WAIT0();
        __syncthreads();   // K/V(kt) visible; other buffer's readers done

        // prefetch next K/V into the other buffer
        if (kt + 1 < N_ / 64) {
            const __half* Kn = Kb + (size_t)(kt + 1) * 64 * DH;
            const __half* Vn = Vb + (size_t)(kt + 1) * 64;
            const uint32_t bufo = (uint32_t)((kt + 1) & 1) * 8192u;
#pragma unroll
            for (int i = 0; i < 4; i++) {
                int idx = i * 128 + tid;
                int r = idx >> 3, ch = idx & 7;
                uint32_t so = (uint32_t)(r * 128 + ((ch ^ (r & 7)) * 16));
                cp16(sbase + AK_OFF + bufo + so, Kn + (size_t)r * DH + ch * 8);
                cp16(sbase + AV_OFF + bufo + so, Vn + (size_t)r * N_ + ch * 8);
            }
        }
        CP_COMMIT();

        if (kt == 0) {
#pragma unroll
            for (int ks = 0; ks < 4; ks++) {
                int ch = ks * 2 + fch;
                int sw = ch ^ (rowAf & 7);
                ldsm4(qfr[ks][0], qfr[ks][1], qfr[ks][2], qfr[ks][3],
                      sbase + AQ_OFF + (uint32_t)(rowAf * 128 + sw * 16));
            }
        }

        const uint32_t sKo = sbase + AK_OFF + (uint32_t)(kt & 1) * 8192u;
        const uint32_t sVo = sbase + AV_OFF + (uint32_t)(kt & 1) * 8192u;

        // ---- S = Q K^T, fp16 accumulate (exp2-domain via pre-scaled Q) ----
        uint32_t s[8][2];
#pragma unroll
        for (int i = 0; i < 8; i++) { s[i][0] = 0u; s[i][1] = 0u; }

#pragma unroll
        for (int ks = 0; ks < 4; ks++) {
#pragma unroll
            for (int nj = 0; nj < 4; nj++) {
                uint32_t b[4];
                int row = nj * 16 + frow;
                int ch = ks * 2 + fch;
                int sw = ch ^ (row & 7);
                ldsm4(b[0], b[1], b[2], b[3], sKo + (uint32_t)(row * 128 + sw * 16));
                mma_f16acc(s[nj * 2 + 0], qfr[ks], b[0], b[2]);
                mma_f16acc(s[nj * 2 + 1], qfr[ks], b[1], b[3]);
            }
        }

        // ---- packed exp2; fp32 row sums ----
#pragma unroll
        for (int nt = 0; nt < 8; nt++) {
            s[nt][0] = ex2_h2(s[nt][0]);
            s[nt][1] = ex2_h2(s[nt][1]);
            float2 f0 = __half22float2(u32_as_h2(s[nt][0]));
            float2 f1 = __half22float2(u32_as_h2(s[nt][1]));
            l_r[0] += f0.x + f0.y;
            l_r[1] += f1.x + f1.y;
        }

        // ---- O += P @ V; P A-frags = s regs directly (layout identity) ----
#pragma unroll
        for (int ks = 0; ks < 4; ks++) {
            uint32_t a[4];
            a[0] = s[2 * ks][0];
            a[1] = s[2 * ks][1];
            a[2] = s[2 * ks + 1][0];
            a[3] = s[2 * ks + 1][1];
#pragma unroll
            for (int nj = 0; nj < 4; nj++) {
                uint32_t b[4];
                int row = nj * 16 + frow;
                int ch = ks * 2 + fch;
                int sw = ch ^ (row & 7);
                ldsm4(b[0], b[1], b[2], b[3], sVo + (uint32_t)(row * 128 + sw * 16));
                mma_f16(o[nj * 2 + 0], a, b[0], b[2]);
                mma_f16(o[nj * 2 + 1], a, b[1], b[3]);
            }
        }
    }

    // ---- final row-sum reduction + epilogue -> g_A (fp16) ----
#pragma unroll
    for (int r = 0; r < 2; r++) {
        l_r[r] += __shfl_xor_sync(0xffffffffu, l_r[r], 1);
        l_r[r] += __shfl_xor_sync(0xffffffffu, l_r[r], 2);
    }
    const int b_ = bh / H_, h = bh % H_;
    const float inv0 = 1.f / l_r[0];
    const float inv1 = 1.f / l_r[1];
    const int n0 = qt * 64 + wid * 16 + g;
    const int n1 = n0 + 8;
#pragma unroll
    for (int nt = 0; nt < 8; nt++) {
        int e = nt * 8 + t * 2;
        *(__half2*)(g_A + ((size_t)(b_ * N_ + n0) * DOUT) + h * DH + e) =
            __float22half2_rn(make_float2(o[nt][0] * inv0, o[nt][1] * inv0));
        *(__half2*)(g_A + ((size_t)(b_ * N_ + n1) * DOUT) + h * DH + e) =
            __float22half2_rn(make_float2(o[nt][2] * inv1, o[nt][3] * inv1));
    }
}

// ===========================================================================
extern "C" void kernel_launch(void* const* d_in, const int* in_sizes, int n_in,
                              void* d_out, int out_size)
{
    (void)in_sizes; (void)n_in; (void)out_size;
    const float* x  = (const float*)d_in[0];
    const float* Wq = (const float*)d_in[1];
    const float* Wk = (const float*)d_in[2];
    const float* Wv = (const float*)d_in[3];
    const float* Wo = (const float*)d_in[4];
    const float* bo = (const float*)d_in[5];
    float* out = (float*)d_out;

    cudaFuncSetAttribute(gemm_qkv, cudaFuncAttributeMaxDynamicSharedMemorySize, GEMM_SMEM);
    cudaFuncSetAttribute(gemm_out, cudaFuncAttributeMaxDynamicSharedMemorySize, OUT_SMEM);
    cudaFuncSetAttribute(attn_mma, cudaFuncAttributeMaxDynamicSharedMemorySize, ATTN_SMEM);

    preround<<<2112, 256>>>(x, Wq, Wk, Wv, Wo);
    gemm_qkv<<<dim3(M_ / 128, 18), 256, GEMM_SMEM>>>();
    attn_mma<<<dim3(N_ / 64, B_ * H_), 128, ATTN_SMEM>>>();
    gemm_out<<<dim3(M_ / 128, DOUT / 64), 256, OUT_SMEM>>>(bo, out);
}

// round 14
// speedup vs baseline: 1.1131x; 1.0320x over previous
#include <cuda_runtime.h>
#include <cuda_fp16.h>
#include <cstdint>

#define B_   8
#define N_   1024
#define DIN  768
#define DOUT 768
#define H_   12
#define DH   64
#define M_   (B_ * N_)   // 8192
#define K_   768

// Scratch (allocation-free: __device__ globals), all fp16 operands
__device__ __align__(128) __half g_X [M_ * K_];
__device__ __align__(128) __half g_Wq[DOUT * DIN];
__device__ __align__(128) __half g_Wk[DOUT * DIN];
__device__ __align__(128) __half g_Wv[DOUT * DIN];
__device__ __align__(128) __half g_Wo[DOUT * DIN];
__device__ __align__(128) __half g_Q[B_ * H_ * N_ * DH];   // [b][h][n][e], pre-scaled
__device__ __align__(128) __half g_K[B_ * H_ * N_ * DH];   // [b][h][n][e]
__device__ __align__(128) __half g_V[B_ * H_ * DH * N_];   // [b][h][e][n] transposed
__device__ __align__(128) __half g_A[B_ * N_ * DOUT];      // attn out [b][n][h*64+e]

// ===========================================================================
// Helpers
// ===========================================================================
__device__ __forceinline__ uint32_t h2_as_u32(__half2 h) {
    union { __half2 h; uint32_t u; } c; c.h = h; return c.u;
}
__device__ __forceinline__ __half2 u32_as_h2(uint32_t u) {
    union { uint32_t u; __half2 h; } c; c.u = u; return c.h;
}
__device__ __forceinline__ uint32_t pack_h2(float lo, float hi) {
    return h2_as_u32(__float22half2_rn(make_float2(lo, hi)));
}

__device__ __forceinline__ uint32_t smem_u32(const void* p) {
    uint32_t a;
    asm("{ .reg .u64 t; cvta.to.shared.u64 t, %1; cvt.u32.u64 %0, t; }"
        : "=r"(a) : "l"(p));
    return a;
}

// packed fp16x2 exp2
__device__ __forceinline__ uint32_t ex2_h2(uint32_t x) {
    uint32_t y;
    asm("ex2.approx.f16x2 %0, %1;" : "=r"(y) : "r"(x));
    return y;
}

__device__ __forceinline__ void ldsm4(uint32_t& r0, uint32_t& r1, uint32_t& r2, uint32_t& r3,
                                      uint32_t addr) {
    asm volatile("ldmatrix.sync.aligned.m8n8.x4.shared.b16 {%0,%1,%2,%3}, [%4];"
        : "=r"(r0), "=r"(r1), "=r"(r2), "=r"(r3) : "r"(addr));
}

// m16n8k16 fp16 mma, fp32 accumulate
__device__ __forceinline__ void mma_f16(float c[4], const uint32_t a[4],
                                        uint32_t b0, uint32_t b1) {
    asm volatile(
        "mma.sync.aligned.m16n8k16.row.col.f32.f16.f16.f32 "
        "{%0,%1,%2,%3}, {%4,%5,%6,%7}, {%8,%9}, {%0,%1,%2,%3};"
        : "+f"(c[0]), "+f"(c[1]), "+f"(c[2]), "+f"(c[3])
        : "r"(a[0]), "r"(a[1]), "r"(a[2]), "r"(a[3]), "r"(b0), "r"(b1));
}

// m16n8k16 fp16 mma, fp16 accumulate
__device__ __forceinline__ void mma_f16acc(uint32_t c[2], const uint32_t a[4],
                                           uint32_t b0, uint32_t b1) {
    asm volatile(
        "mma.sync.aligned.m16n8k16.row.col.f16.f16.f16.f16 "
        "{%0,%1}, {%2,%3,%4,%5}, {%6,%7}, {%0,%1};"
        : "+r"(c[0]), "+r"(c[1])
        : "r"(a[0]), "r"(a[1]), "r"(a[2]), "r"(a[3]), "r"(b0), "r"(b1));
}

__device__ __forceinline__ void cp16(uint32_t saddr, const void* gptr) {
    asm volatile("cp.async.cg.shared.global [%0], [%1], 16;"
        :: "r"(saddr), "l"(gptr) : "memory");
}
#define CP_COMMIT() asm volatile("cp.async.commit_group;" ::: "memory")
#define CP_WAIT0()  asm volatile("cp.async.wait_group 0;" ::: "memory")
#define CP_WAIT1()  asm volatile("cp.async.wait_group 1;" ::: "memory")

// ===========================================================================
// Pre-round x and weights to fp16 (one pass)
// ===========================================================================
__global__ __launch_bounds__(256)
void preround(const float* __restrict__ x,
              const float* __restrict__ wq, const float* __restrict__ wk,
              const float* __restrict__ wv, const float* __restrict__ wo)
{
    constexpr int XV = M_ * K_ / 8;
    constexpr int WV = DOUT * DIN / 8;
    constexpr int TOT = XV + 4 * WV;
    for (int i = blockIdx.x * blockDim.x + threadIdx.x; i < TOT;
         i += gridDim.x * blockDim.x) {
        const float4* src; __half* dst; int off;
        if (i < XV) { src = (const float4*)x; dst = g_X; off = i; }
        else {
            int j = i - XV, seg = j / WV; off = j % WV;
            src = (seg == 0) ? (const float4*)wq : (seg == 1) ? (const float4*)wk
                : (seg == 2) ? (const float4*)wv : (const float4*)wo;
            dst = (seg == 0) ? g_Wq : (seg == 1) ? g_Wk
                : (seg == 2) ? g_Wv : g_Wo;
        }
        float4 v0 = src[2 * off];
        float4 v1 = src[2 * off + 1];
        uint4 u;
        u.x = pack_h2(v0.x, v0.y);
        u.y = pack_h2(v0.z, v0.w);
        u.z = pack_h2(v1.x, v1.y);
        u.w = pack_h2(v1.z, v1.w);
        *(uint4*)(dst + 8 * (size_t)off) = u;
    }
}

// ===========================================================================
// QKV GEMM: fp16 accumulate, 256x128 CTA tiles (copy-issue per MAC 0.75x,
// ldsm:mma 0.25, grid 576 = 1.95 waves). 256 threads = 8 warps 4x2,
// warp tile 64x64, k-tile 64, 2-stage cp.async (A 32KB + B 16KB per stage).
// ===========================================================================
#define QKV_STAGE 49152
#define QKV_SMEM  (2 * QKV_STAGE)

__global__ __launch_bounds__(256, 2)
void gemm_qkv()
{
    extern __shared__ char smc[];
    const uint32_t sbase = smem_u32(smc);

    const int tid  = threadIdx.x;
    const int wid  = tid >> 5;
    const int lane = tid & 31;
    const int wm   = wid >> 1;   // 0..3
    const int wn   = wid & 1;    // 0..1

    const int m0    = blockIdx.x * 256;
    const int ntile = blockIdx.y;
    const int wsel  = ntile / 6;
    const __half* Bmat = (wsel == 0) ? g_Wq : (wsel == 1) ? g_Wk : g_Wv;
    const int c0 = (ntile % 6) * 128;

    const __half* Ag = g_X + (size_t)m0 * K_;
    const __half* Bg = Bmat + (size_t)c0 * K_;

    uint32_t acc[4][8][2];
#pragma unroll
    for (int i = 0; i < 4; i++)
#pragma unroll
        for (int j = 0; j < 8; j++) { acc[i][j][0] = 0u; acc[i][j][1] = 0u; }

    const int frow = ((lane >> 3) & 1) * 8 + (lane & 7);
    const int fch  = lane >> 4;
    const int rowA_base = wm * 64 + frow;
    const int rowB_base = wn * 64 + frow;

    constexpr int KT = K_ / 64;   // 12

    auto issue = [&](int kt) {
        const uint32_t so = sbase + (uint32_t)(kt & 1) * QKV_STAGE;
        // A: 256 rows x 128B = 2048 chunks -> 8 per thread
#pragma unroll
        for (int i = 0; i < 8; i++) {
            int idx = i * 256 + tid;
            int r = idx >> 3, ch = idx & 7;
            int sw = ch ^ (r & 7);
            cp16(so + (uint32_t)(r * 128 + sw * 16),
                 Ag + (size_t)r * K_ + kt * 64 + ch * 8);
        }
        // B: 128 rows x 128B = 1024 chunks -> 4 per thread
#pragma unroll
        for (int i = 0; i < 4; i++) {
            int idx = i * 256 + tid;
            int r = idx >> 3, ch = idx & 7;
            int sw = ch ^ (r & 7);
            cp16(so + 32768u + (uint32_t)(r * 128 + sw * 16),
                 Bg + (size_t)r * K_ + kt * 64 + ch * 8);
        }
    };

    issue(0); CP_COMMIT();
    issue(1); CP_COMMIT();

    for (int kt = 0; kt < KT; kt++) {
        CP_WAIT1();
        __syncthreads();   // stage kt&1 data ready for all warps

        const uint32_t sAo = sbase + (uint32_t)(kt & 1) * QKV_STAGE;
        const uint32_t sBo = sAo + 32768u;
#pragma unroll
        for (int ks = 0; ks < 4; ks++) {
            uint32_t afr[4][4];
#pragma unroll
            for (int mi = 0; mi < 4; mi++) {
                int row = rowA_base + mi * 16;
                int ch  = ks * 2 + fch;
                int sw  = ch ^ (row & 7);
                ldsm4(afr[mi][0], afr[mi][1], afr[mi][2], afr[mi][3],
                      sAo + (uint32_t)(row * 128 + sw * 16));
            }
#pragma unroll
            for (int nj = 0; nj < 4; nj++) {
                uint32_t b[4];
                int row = rowB_base + nj * 16;
                int ch  = ks * 2 + fch;
                int sw  = ch ^ (row & 7);
                ldsm4(b[0], b[1], b[2], b[3], sBo + (uint32_t)(row * 128 + sw * 16));
#pragma unroll
                for (int mi = 0; mi < 4; mi++) {
                    mma_f16acc(acc[mi][nj * 2 + 0], afr[mi], b[0], b[2]);
                    mma_f16acc(acc[mi][nj * 2 + 1], afr[mi], b[1], b[3]);
                }
            }
        }

        __syncthreads();   // all warps done reading stage kt&1
        if (kt + 2 < KT) issue(kt + 2);
        CP_COMMIT();
    }

    // Direct epilogue
    const int g = lane >> 2, t = lane & 3;
    const float qscale = 0.125f * 1.44269504088896f;
#pragma unroll
    for (int mi = 0; mi < 4; mi++) {
#pragma unroll
        for (int nt = 0; nt < 8; nt++) {
            int cw = c0 + wn * 64 + nt * 8 + t * 2;
            int r0 = m0 + wm * 64 + mi * 16 + g;
            int h = cw >> 6, e = cw & 63;
            if (wsel < 2) {
                __half* outp = (wsel == 0) ? g_Q : g_K;
                float sc = (wsel == 0) ? qscale : 1.f;
#pragma unroll
                for (int rr = 0; rr < 2; rr++) {
                    int m = r0 + rr * 8;
                    int b = m >> 10, n = m & (N_ - 1);
                    float2 f = __half22float2(u32_as_h2(acc[mi][nt][rr]));
                    __half2 v = __float22half2_rn(make_float2(f.x * sc, f.y * sc));
                    *(__half2*)(outp + (((size_t)(b * H_ + h) * N_ + n) * DH) + e) = v;
                }
            } else {
                // V transposed: [b][h][e][n]
#pragma unroll
                for (int rr = 0; rr < 2; rr++) {
                    int m = r0 + rr * 8;
                    int b = m >> 10, n = m & (N_ - 1);
                    __half2 hv = u32_as_h2(acc[mi][nt][rr]);
                    size_t base = ((size_t)(b * H_ + h) * DH + e) * N_ + n;
                    g_V[base]      = __low2half(hv);
                    g_V[base + N_] = __high2half(hv);
                }
            }
        }
    }
}

// ===========================================================================
// Output-proj GEMM (round-13 winner): fp32 accumulate, 128x64 tiles, grid 768.
// 256 threads = 8 warps 4x2, warp tile 32x32, k-tile 64, 3-stage cp.async.
// ===========================================================================
#define OUT_SMEM (3 * 24576)

__global__ __launch_bounds__(256, 2)
void gemm_out(const float* __restrict__ bo, float* __restrict__ out)
{
    extern __shared__ char smc[];
    const uint32_t sbase = smem_u32(smc);

    const int tid  = threadIdx.x;
    const int wid  = tid >> 5;
    const int lane = tid & 31;
    const int wm   = wid >> 1;   // 0..3
    const int wn   = wid & 1;    // 0..1

    const int m0 = blockIdx.x * 128;
    const int c0 = blockIdx.y * 64;

    const __half* Ag = g_A + (size_t)m0 * K_;
    const __half* Bg = g_Wo + (size_t)c0 * K_;

    float acc[2][4][4];
#pragma unroll
    for (int i = 0; i < 2; i++)
#pragma unroll
        for (int j = 0; j < 4; j++)
#pragma unroll
            for (int k = 0; k < 4; k++) acc[i][j][k] = 0.f;

    const int frow = ((lane >> 3) & 1) * 8 + (lane & 7);
    const int fch  = lane >> 4;
    const int rowA_base = wm * 32 + frow;
    const int rowB_base = wn * 32 + frow;

    constexpr int KT = K_ / 64;

    auto issue = [&](int kt) {
        const uint32_t so = sbase + (uint32_t)(kt % 3) * 24576u;
#pragma unroll
        for (int i = 0; i < 4; i++) {
            int idx = i * 256 + tid;
            int r = idx >> 3, ch = idx & 7;
            int sw = ch ^ (r & 7);
            cp16(so + (uint32_t)(r * 128 + sw * 16),
                 Ag + (size_t)r * K_ + kt * 64 + ch * 8);
        }
#pragma unroll
        for (int i = 0; i < 2; i++) {
            int idx = i * 256 + tid;
            int r = idx >> 3, ch = idx & 7;
            int sw = ch ^ (r & 7);
            cp16(so + 16384u + (uint32_t)(r * 128 + sw * 16),
                 Bg + (size_t)r * K_ + kt * 64 + ch * 8);
        }
    };

    issue(0); CP_COMMIT();
    issue(1); CP_COMMIT();

    for (int kt = 0; kt < KT; kt++) {
        CP_WAIT1();
        __syncthreads();

        if (kt + 2 < KT) issue(kt + 2);
        CP_COMMIT();

        const uint32_t sAo = sbase + (uint32_t)(kt % 3) * 24576u;
        const uint32_t sBo = sAo + 16384u;
#pragma unroll
        for (int ks = 0; ks < 4; ks++) {
            uint32_t afr[2][4];
#pragma unroll
            for (int mi = 0; mi < 2; mi++) {
                int row = rowA_base + mi * 16;
                int ch  = ks * 2 + fch;
                int sw  = ch ^ (row & 7);
                ldsm4(afr[mi][0], afr[mi][1], afr[mi][2], afr[mi][3],
                      sAo + (uint32_t)(row * 128 + sw * 16));
            }
            uint32_t bfr[2][4];
#pragma unroll
            for (int nj = 0; nj < 2; nj++) {
                int row = rowB_base + nj * 16;
                int ch  = ks * 2 + fch;
                int sw  = ch ^ (row & 7);
                ldsm4(bfr[nj][0], bfr[nj][1], bfr[nj][2], bfr[nj][3],
                      sBo + (uint32_t)(row * 128 + sw * 16));
            }
#pragma unroll
            for (int mi = 0; mi < 2; mi++)
#pragma unroll
                for (int nj = 0; nj < 2; nj++) {
                    mma_f16(acc[mi][nj * 2 + 0], afr[mi], bfr[nj][0], bfr[nj][2]);
                    mma_f16(acc[mi][nj * 2 + 1], afr[mi], bfr[nj][1], bfr[nj][3]);
                }
        }
    }

    const int g = lane >> 2, t = lane & 3;
#pragma unroll
    for (int mi = 0; mi < 2; mi++) {
#pragma unroll
        for (int nt = 0; nt < 4; nt++) {
            int cw = c0 + wn * 32 + nt * 8 + t * 2;
            int r0 = m0 + wm * 32 + mi * 16 + g;
            float2 bias = *(const float2*)(bo + cw);
#pragma unroll
            for (int rr = 0; rr < 2; rr++) {
                int m = r0 + rr * 8;
                float2 v = make_float2(acc[mi][nt][rr * 2] + bias.x,
                                       acc[mi][nt][rr * 2 + 1] + bias.y);
                *(float2*)(out + (size_t)m * DOUT + cw) = v;
            }
        }
    }
}

// ===========================================================================
// Flash attention (round-13 winner): 64-row q-tiles, 128 threads, 4 CTAs/SM.
// S fp16-accum (C-frags ARE the PV A-frags), packed ex2, unnormalized softmax.
// smem: Q @0 (8KB), K @8192 (2x8KB), V @24576 (2x8KB) = 40KB
// ===========================================================================
#define AQ_OFF 0u
#define AK_OFF 8192u
#define AV_OFF 24576u
#define ATTN_SMEM 40960

__global__ __launch_bounds__(128, 4)
void attn_mma()
{
    extern __shared__ char smc[];
    const uint32_t sbase = smem_u32(smc);

    const int qt = blockIdx.x;        // 0..15 (64 rows each)
    const int bh = blockIdx.y;        // 0..95
    const __half* Qb = g_Q + (size_t)bh * N_ * DH;
    const __half* Kb = g_K + (size_t)bh * N_ * DH;
    const __half* Vb = g_V + (size_t)bh * DH * N_;   // [e][n]

    const int tid  = threadIdx.x;
    const int wid  = tid >> 5;        // 0..3
    const int lane = tid & 31;
    const int g    = lane >> 2;
    const int t    = lane & 3;

    const int frow = ((lane >> 3) & 1) * 8 + (lane & 7);
    const int fch  = lane >> 4;
    const int rowAf = wid * 16 + frow;   // Q A-frag row (0..63)

    // ---- prologue: Q tile (8KB) + K/V tile 0 (8KB each) ----
#pragma unroll
    for (int i = 0; i < 4; i++) {
        int idx = i * 128 + tid;
        int r = idx >> 3, ch = idx & 7;
        uint32_t so = (uint32_t)(r * 128 + ((ch ^ (r & 7)) * 16));
        cp16(sbase + AQ_OFF + so, Qb + (size_t)(qt * 64 + r) * DH + ch * 8);
        cp16(sbase + AK_OFF + so, Kb + (size_t)r * DH + ch * 8);
        cp16(sbase + AV_OFF + so, Vb + (size_t)r * N_ + ch * 8);
    }
    CP_COMMIT();

    float l_r[2] = {0.f, 0.f};
    float o[8][4];
#pragma unroll
    for (int i = 0; i < 8; i++)
#pragma unroll
        for (int j = 0; j < 4; j++) o[i][j] = 0.f;

    uint32_t qfr[4][4];   // cached Q fragments

    for (int kt = 0; kt < N_ / 64; kt++) {
        CP_WAIT0();
        __syncthreads();   // K/V(kt) visible; other buffer's readers done

        // prefetch next K/V into the other buffer
        if (kt + 1 < N_ / 64) {
            const __half* Kn = Kb + (size_t)(kt + 1) * 64 * DH;
            const __half* Vn = Vb + (size_t)(kt + 1) * 64;
            const uint32_t bufo = (uint32_t)((kt + 1) & 1) * 8192u;
#pragma unroll
            for (int i = 0; i < 4; i++) {
                int idx = i * 128 + tid;
                int r = idx >> 3, ch = idx & 7;
                uint32_t so = (uint32_t)(r * 128 + ((ch ^ (r & 7)) * 16));
                cp16(sbase + AK_OFF + bufo + so, Kn + (size_t)r * DH + ch * 8);
                cp16(sbase + AV_OFF + bufo + so, Vn + (size_t)r * N_ + ch * 8);
            }
        }
        CP_COMMIT();

        if (kt == 0) {
#pragma unroll
            for (int ks = 0; ks < 4; ks++) {
                int ch = ks * 2 + fch;
                int sw = ch ^ (rowAf & 7);
                ldsm4(qfr[ks][0], qfr[ks][1], qfr[ks][2], qfr[ks][3],
                      sbase + AQ_OFF + (uint32_t)(rowAf * 128 + sw * 16));
            }
        }

        const uint32_t sKo = sbase + AK_OFF + (uint32_t)(kt & 1) * 8192u;
        const uint32_t sVo = sbase + AV_OFF + (uint32_t)(kt & 1) * 8192u;

        // ---- S = Q K^T, fp16 accumulate (exp2-domain via pre-scaled Q) ----
        uint32_t s[8][2];
#pragma unroll
        for (int i = 0; i < 8; i++) { s[i][0] = 0u; s[i][1] = 0u; }

#pragma unroll
        for (int ks = 0; ks < 4; ks++) {
#pragma unroll
            for (int nj = 0; nj < 4; nj++) {
                uint32_t b[4];
                int row = nj * 16 + frow;
                int ch = ks * 2 + fch;
                int sw = ch ^ (row & 7);
                ldsm4(b[0], b[1], b[2], b[3], sKo + (uint32_t)(row * 128 + sw * 16));
                mma_f16acc(s[nj * 2 + 0], qfr[ks], b[0], b[2]);
                mma_f16acc(s[nj * 2 + 1], qfr[ks], b[1], b[3]);
            }
        }

        // ---- packed exp2; fp32 row sums ----
#pragma unroll
        for (int nt = 0; nt < 8; nt++) {
            s[nt][0] = ex2_h2(s[nt][0]);
            s[nt][1] = ex2_h2(s[nt][1]);
            float2 f0 = __half22float2(u32_as_h2(s[nt][0]));
            float2 f1 = __half22float2(u32_as_h2(s[nt][1]));
            l_r[0] += f0.x + f0.y;
            l_r[1] += f1.x + f1.y;
        }

        // ---- O += P @ V; P A-frags = s regs directly (layout identity) ----
#pragma unroll
        for (int ks = 0; ks < 4; ks++) {
            uint32_t a[4];
            a[0] = s[2 * ks][0];
            a[1] = s[2 * ks][1];
            a[2] = s[2 * ks + 1][0];
            a[3] = s[2 * ks + 1][1];
#pragma unroll
            for (int nj = 0; nj < 4; nj++) {
                uint32_t b[4];
                int row = nj * 16 + frow;
                int ch = ks * 2 + fch;
                int sw = ch ^ (row & 7);
                ldsm4(b[0], b[1], b[2], b[3], sVo + (uint32_t)(row * 128 + sw * 16));
                mma_f16(o[nj * 2 + 0], a, b[0], b[2]);
                mma_f16(o[nj * 2 + 1], a, b[1], b[3]);
            }
        }
    }

    // ---- final row-sum reduction + epilogue -> g_A (fp16) ----
#pragma unroll
    for (int r = 0; r < 2; r++) {
        l_r[r] += __shfl_xor_sync(0xffffffffu, l_r[r], 1);
        l_r[r] += __shfl_xor_sync(0xffffffffu, l_r[r], 2);
    }
    const int b_ = bh / H_, h = bh % H_;
    const float inv0 = 1.f / l_r[0];
    const float inv1 = 1.f / l_r[1];
    const int n0 = qt * 64 + wid * 16 + g;
    const int n1 = n0 + 8;
#pragma unroll
    for (int nt = 0; nt < 8; nt++) {
        int e = nt * 8 + t * 2;
        *(__half2*)(g_A + ((size_t)(b_ * N_ + n0) * DOUT) + h * DH + e) =
            __float22half2_rn(make_float2(o[nt][0] * inv0, o[nt][1] * inv0));
        *(__half2*)(g_A + ((size_t)(b_ * N_ + n1) * DOUT) + h * DH + e) =
            __float22half2_rn(make_float2(o[nt][2] * inv1, o[nt][3] * inv1));
    }
}

// ===========================================================================
extern "C" void kernel_launch(void* const* d_in, const int* in_sizes, int n_in,
                              void* d_out, int out_size)
{
    (void)in_sizes; (void)n_in; (void)out_size;
    const float* x  = (const float*)d_in[0];
    const float* Wq = (const float*)d_in[1];
    const float* Wk = (const float*)d_in[2];
    const float* Wv = (const float*)d_in[3];
    const float* Wo = (const float*)d_in[4];
    const float* bo = (const float*)d_in[5];
    float* out = (float*)d_out;

    cudaFuncSetAttribute(gemm_qkv, cudaFuncAttributeMaxDynamicSharedMemorySize, QKV_SMEM);
    cudaFuncSetAttribute(gemm_out, cudaFuncAttributeMaxDynamicSharedMemorySize, OUT_SMEM);
    cudaFuncSetAttribute(attn_mma, cudaFuncAttributeMaxDynamicSharedMemorySize, ATTN_SMEM);

    preround<<<2112, 256>>>(x, Wq, Wk, Wv, Wo);
    gemm_qkv<<<dim3(M_ / 256, 18), 256, QKV_SMEM>>>();
    attn_mma<<<dim3(N_ / 64, B_ * H_), 128, ATTN_SMEM>>>();
    gemm_out<<<dim3(M_ / 128, DOUT / 64), 256, OUT_SMEM>>>(bo, out);
}